// round 8
// baseline (speedup 1.0000x reference)
#include <cuda_runtime.h>
#include <math.h>

// SVRaster: 4096 rays vs 16^3 regular voxel grid on [-1,1]^3.
//
// 16 threads per ray; lane j owns slab j (traversal order) along the ray's
// dominant axis D. Since |dU|,|dV| <= |dD|, a slab has at most ONE U crossing
// and ONE V crossing => at most 3 visited cells, all inside the 2x2 candidate
// set {u0,u1} x {v0,v1} (entry/exit cells). The two middle candidates are
// provably mutually exclusive, so compositing in fixed order C00,C10,C01,C11
// is exact. Every candidate is tested with the EXACT reference slab
// arithmetic (planes i*0.125-1 are exact fp32 == ctr +/- half), so spurious
// candidates are rejected identically to the reference; hit set & order match.
// Compositing uses linearity in incoming transmittance: local composite with
// T=1, then a width-16 shuffle prefix-product supplies each lane's true T0.

#define GN       16
#define CELL     0.125f
#define BMIN     (-1.0f)
#define MAX_HITS 100
#define GROUP    16
#define BLOCK    128

__device__ __forceinline__ float safe_dir(float d) {
    return (fabsf(d) < 1e-8f) ? ((d >= 0.0f) ? 1e-8f : -1e-8f) : d;
}

__device__ __forceinline__ void composite(bool hit, int vox, float tn, float tf,
                                          const float* __restrict__ vdens,
                                          const float* __restrict__ vcol,
                                          float& T, float& lr, float& lg,
                                          float& lb, float& ldep)
{
    float sg = __expf(__ldg(&vdens[vox]));
    float c0 = __ldg(&vcol[3 * vox + 0]);
    float c1 = __ldg(&vcol[3 * vox + 1]);
    float c2 = __ldg(&vcol[3 * vox + 2]);
    float dt = tf - tn;
    float alpha = 1.0f - __expf(-sg * dt);
    float w = hit ? (T * alpha) : 0.0f;
    lr   = fmaf(w, c0, lr);
    lg   = fmaf(w, c1, lg);
    lb   = fmaf(w, c2, lb);
    ldep = fmaf(w, 0.5f * (tn + tf), ldep);
    T   *= hit ? (1.0f - alpha + 1e-10f) : 1.0f;
}

__global__ void __launch_bounds__(BLOCK)
svraster_kernel(const float* __restrict__ ro,
                const float* __restrict__ rd,
                const float* __restrict__ vdens,
                const float* __restrict__ vcol,
                float* __restrict__ out,
                int R)
{
    const unsigned FULL = 0xffffffffu;
    const int tid = threadIdx.x;
    const int j   = tid & (GROUP - 1);                     // lane in ray group
    const int r   = (blockIdx.x * BLOCK + tid) >> 4;       // ray id

    const float ox = ro[3 * r + 0], oy = ro[3 * r + 1], oz = ro[3 * r + 2];
    const float dxr = rd[3 * r + 0], dyr = rd[3 * r + 1], dzr = rd[3 * r + 2];

    const float ivx = 1.0f / safe_dir(dxr);
    const float ivy = 1.0f / safe_dir(dyr);
    const float ivz = 1.0f / safe_dir(dzr);

    // Scene-box slab (exact same planes as grid faces).
    float tx0 = (BMIN - ox) * ivx, tx1 = (1.0f - ox) * ivx;
    float ty0 = (BMIN - oy) * ivy, ty1 = (1.0f - oy) * ivy;
    float tz0 = (BMIN - oz) * ivz, tz1 = (1.0f - oz) * ivz;
    float tEnter = fmaxf(fmaxf(fminf(tx0, tx1), fminf(ty0, ty1)), fminf(tz0, tz1));
    float tExit  = fminf(fminf(fmaxf(tx0, tx1), fmaxf(ty0, ty1)), fmaxf(tz0, tz1));
    tEnter = fmaxf(tEnter, 0.0f);

    // Dominant axis D = argmax |d|;  (D,U,V) permutation:
    // axis0: (x,y,z)  axis1: (y,x,z)  axis2: (z,x,y)
    float adx = fabsf(dxr), ady = fabsf(dyr), adz = fabsf(dzr);
    int axis = (adx >= ady && adx >= adz) ? 0 : ((ady >= adz) ? 1 : 2);

    float oD = (axis == 0) ? ox : ((axis == 1) ? oy : oz);
    float oU = (axis == 0) ? oy : ox;
    float oV = (axis == 2) ? oy : oz;
    float iD = (axis == 0) ? ivx : ((axis == 1) ? ivy : ivz);
    float iU = (axis == 0) ? ivy : ivx;
    float iV = (axis == 2) ? ivy : ivz;
    float dUr = (axis == 0) ? dyr : dxr;
    float dVr = (axis == 2) ? dyr : dzr;

    const int sD = (iD >= 0.0f) ? 1 : -1;
    const int sU = (iU >= 0.0f) ? 1 : -1;
    const int sV = (iV >= 0.0f) ? 1 : -1;
    const int exU = (sU > 0) ? 1 : 0;
    const int exV = (sV > 0) ? 1 : 0;

    // Lane j -> slab k in traversal order.
    const int k = (sD > 0) ? j : (GN - 1 - j);

    // Exact D-axis crossings of slab k.
    float pk0 = fmaf((float)k,       CELL, BMIN);
    float pk1 = fmaf((float)(k + 1), CELL, BMIN);
    float tA = (pk0 - oD) * iD;
    float tB = (pk1 - oD) * iD;
    float lDk = fminf(tA, tB);
    float nDk = fmaxf(tA, tB);
    float lD0 = fmaxf(lDk, 0.0f);

    float w0 = fmaxf(lDk, tEnter);
    float w1 = fminf(nDk, tExit);
    bool alive = (w1 > w0);

    // Early zero-fill of idx row (stores retire under the compute shadow).
    float* out_idx = out + (size_t)5 * R + (size_t)r * MAX_HITS;
    {
        float4 z4 = make_float4(0.0f, 0.0f, 0.0f, 0.0f);
        ((float4*)out_idx)[j] = z4;
        if (j < MAX_HITS / 4 - GROUP) ((float4*)out_idx)[j + GROUP] = z4;
    }

    // ---- U axis: entry cell u0 (with exact-crossing correction) + exit u1 ----
    float pu = fmaf(dUr, w0, oU);
    int u0 = (int)floorf((pu - BMIN) * 8.0f);
    float lu0 = (fmaf((float)(u0 + 1 - exU), CELL, BMIN) - oU) * iU;
    float nu0 = (fmaf((float)(u0 + exU),     CELL, BMIN) - oU) * iU;
    if      (nu0 < w0) u0 += sU;       // floor undershot
    else if (lu0 > w0) u0 -= sU;       // floor overshot
    lu0 = (fmaf((float)(u0 + 1 - exU), CELL, BMIN) - oU) * iU;
    nu0 = (fmaf((float)(u0 + exU),     CELL, BMIN) - oU) * iU;
    bool stepU = (nu0 < w1);
    int   u1  = u0 + (stepU ? sU : 0);
    float lu1 = stepU ? nu0 : lu0;
    float nu1 = stepU ? ((fmaf((float)(u1 + exU), CELL, BMIN) - oU) * iU) : nu0;

    // ---- V axis ----
    float pv = fmaf(dVr, w0, oV);
    int v0 = (int)floorf((pv - BMIN) * 8.0f);
    float lv0 = (fmaf((float)(v0 + 1 - exV), CELL, BMIN) - oV) * iV;
    float nv0 = (fmaf((float)(v0 + exV),     CELL, BMIN) - oV) * iV;
    if      (nv0 < w0) v0 += sV;
    else if (lv0 > w0) v0 -= sV;
    lv0 = (fmaf((float)(v0 + 1 - exV), CELL, BMIN) - oV) * iV;
    nv0 = (fmaf((float)(v0 + exV),     CELL, BMIN) - oV) * iV;
    bool stepV = (nv0 < w1);
    int   v1  = v0 + (stepV ? sV : 0);
    float lv1 = stepV ? nv0 : lv0;
    float nv1 = stepV ? ((fmaf((float)(v1 + exV), CELL, BMIN) - oV) * iV) : nv0;

    // ---- 2x2 candidate tests (exact reference slab arithmetic) ----
    bool inbU0 = ((unsigned)u0 < GN), inbU1 = ((unsigned)u1 < GN);
    bool inbV0 = ((unsigned)v0 < GN), inbV1 = ((unsigned)v1 < GN);

    float tn00 = fmaxf(fmaxf(lu0, lv0), lD0), tf00 = fminf(fminf(nu0, nv0), nDk);
    float tn10 = fmaxf(fmaxf(lu1, lv0), lD0), tf10 = fminf(fminf(nu1, nv0), nDk);
    float tn01 = fmaxf(fmaxf(lu0, lv1), lD0), tf01 = fminf(fminf(nu0, nv1), nDk);
    float tn11 = fmaxf(fmaxf(lu1, lv1), lD0), tf11 = fminf(fminf(nu1, nv1), nDk);

    bool h00 = alive && inbU0 && inbV0 && (tf00 > tn00);
    bool h10 = alive && stepU && inbU1 && inbV0 && (tf10 > tn10);
    bool h01 = alive && stepV && inbU0 && inbV1 && (tf01 > tn01);
    bool h11 = alive && stepU && stepV && inbU1 && inbV1 && (tf11 > tn11);

    // Clamped indices for safe unconditional loads.
    int uc0 = min(GN - 1, max(0, u0)), uc1 = min(GN - 1, max(0, u1));
    int vc0 = min(GN - 1, max(0, v0)), vc1 = min(GN - 1, max(0, v1));

    // Voxel index for permuted (k, u, v).
    #define VOXI(UC, VC) \
        ((((axis == 0) ? k : (UC)) * GN + ((axis == 0) ? (UC) : ((axis == 1) ? k : (VC)))) * GN \
         + ((axis == 2) ? k : (VC)))
    int vox00 = VOXI(uc0, vc0);
    int vox10 = VOXI(uc1, vc0);
    int vox01 = VOXI(uc0, vc1);
    int vox11 = VOXI(uc1, vc1);
    #undef VOXI

    // ---- composite in tn order (C10/C01 mutually exclusive => fixed order) ----
    float Tl = 1.0f, lr = 0.0f, lg = 0.0f, lb = 0.0f, ldep = 0.0f;
    composite(h00, vox00, tn00, tf00, vdens, vcol, Tl, lr, lg, lb, ldep);
    composite(h10, vox10, tn10, tf10, vdens, vcol, Tl, lr, lg, lb, ldep);
    composite(h01, vox01, tn01, tf01, vdens, vcol, Tl, lr, lg, lb, ldep);
    composite(h11, vox11, tn11, tf11, vdens, vcol, Tl, lr, lg, lb, ldep);

    int cnt = (h00 ? 1 : 0) + (h10 ? 1 : 0) + (h01 ? 1 : 0) + (h11 ? 1 : 0);

    // ---- width-16 scans: hit-count prefix sum + transmittance prefix product
    float prod = Tl;
    int   csum = cnt;
    #pragma unroll
    for (int d = 1; d < GROUP; d <<= 1) {
        float p = __shfl_up_sync(FULL, prod, d, GROUP);
        int   c = __shfl_up_sync(FULL, csum, d, GROUP);
        if (j >= d) { prod *= p; csum += c; }
    }
    float T0 = __shfl_up_sync(FULL, prod, 1, GROUP);
    if (j == 0) T0 = 1.0f;
    int base  = csum - cnt;
    int total = __shfl_sync(FULL, csum, GROUP - 1, GROUP);

    // ---- reductions: rgb/depth scale linearly with incoming T0 ----
    float sr = T0 * lr, sg2 = T0 * lg, sb = T0 * lb, sd = T0 * ldep;
    #pragma unroll
    for (int d = GROUP / 2; d > 0; d >>= 1) {
        sr  += __shfl_xor_sync(FULL, sr,  d, GROUP);
        sg2 += __shfl_xor_sync(FULL, sg2, d, GROUP);
        sb  += __shfl_xor_sync(FULL, sb,  d, GROUP);
        sd  += __shfl_xor_sync(FULL, sd,  d, GROUP);
    }

    // ---- outputs ----
    __syncwarp(FULL);   // zero-fill (other lanes) before hit overwrites

    int p = base;
    if (h00) out_idx[p++] = (float)vox00;
    if (h10) out_idx[p++] = (float)vox10;
    if (h01) out_idx[p++] = (float)vox01;
    if (h11) out_idx[p++] = (float)vox11;

    if (j == 0) {
        out[3 * r + 0] = sr;
        out[3 * r + 1] = sg2;
        out[3 * r + 2] = sb;
        out[(size_t)3 * R + r] = sd;
        out[(size_t)4 * R + r] = (float)total;
    }
}

extern "C" void kernel_launch(void* const* d_in, const int* in_sizes, int n_in,
                              void* d_out, int out_size)
{
    const float* ro    = (const float*)d_in[0];
    const float* rd    = (const float*)d_in[1];
    const float* vdens = (const float*)d_in[4];
    const float* vcol  = (const float*)d_in[5];
    float* out = (float*)d_out;

    int R = in_sizes[0] / 3;
    int total_threads = R * GROUP;
    int blocks = (total_threads + BLOCK - 1) / BLOCK;
    svraster_kernel<<<blocks, BLOCK>>>(ro, rd, vdens, vcol, out, R);
}

// round 9
// speedup vs baseline: 1.0257x; 1.0257x over previous
#include <cuda_runtime.h>
#include <math.h>

// SVRaster: 4096 rays vs 16^3 regular voxel grid on [-1,1]^3.
//
// ONE WARP PER RAY. Lane l = 2*j + h: slab j (traversal order along the
// dominant axis D), half h. Since |dU|,|dV| <= |dD| a slab has at most one
// U crossing and one V crossing => visited cells lie in {u0,u1} x {v0,v1}.
// Half 0 tests (u0,v0),(u1,v0); half 1 tests (u0,v1),(u1,v1). The two middle
// candidates are mutually exclusive, so lane order == exact tn order.
// All hit decisions use the EXACT reference slab arithmetic (planes
// i*0.125-1 are exact fp32 == ctr +/- half): hit set & order == reference.
// Compositing uses linearity in incoming transmittance: local composite with
// T=1, then a width-32 shuffle prefix-product supplies each lane's true T0.

#define GN       16
#define CELL     0.125f
#define BMIN     (-1.0f)
#define MAX_HITS 100
#define BLOCK    128

__device__ __forceinline__ float safe_dir(float d) {
    return (fabsf(d) < 1e-8f) ? ((d >= 0.0f) ? 1e-8f : -1e-8f) : d;
}

__global__ void __launch_bounds__(BLOCK)
svraster_kernel(const float* __restrict__ ro,
                const float* __restrict__ rd,
                const float* __restrict__ vdens,
                const float* __restrict__ vcol,
                float* __restrict__ out,
                int R)
{
    const unsigned FULL = 0xffffffffu;
    const int tid  = threadIdx.x;
    const int lane = tid & 31;
    const int j    = lane >> 1;          // slab index (traversal order)
    const int h    = lane & 1;           // half: 0 -> v0 row, 1 -> v1 row
    const int r    = (blockIdx.x * BLOCK + tid) >> 5;   // ray id (1 warp/ray)

    const float ox = ro[3 * r + 0], oy = ro[3 * r + 1], oz = ro[3 * r + 2];
    const float dxr = rd[3 * r + 0], dyr = rd[3 * r + 1], dzr = rd[3 * r + 2];

    const float ivx = 1.0f / safe_dir(dxr);
    const float ivy = 1.0f / safe_dir(dyr);
    const float ivz = 1.0f / safe_dir(dzr);

    // Scene-box slab (exact same planes as grid faces).
    float tx0 = (BMIN - ox) * ivx, tx1 = (1.0f - ox) * ivx;
    float ty0 = (BMIN - oy) * ivy, ty1 = (1.0f - oy) * ivy;
    float tz0 = (BMIN - oz) * ivz, tz1 = (1.0f - oz) * ivz;
    float tEnter = fmaxf(fmaxf(fminf(tx0, tx1), fminf(ty0, ty1)), fminf(tz0, tz1));
    float tExit  = fminf(fminf(fmaxf(tx0, tx1), fmaxf(ty0, ty1)), fmaxf(tz0, tz1));
    tEnter = fmaxf(tEnter, 0.0f);

    // Dominant axis D = argmax |d|;  (D,U,V) permutation:
    // axis0: (x,y,z)  axis1: (y,x,z)  axis2: (z,x,y)
    float adx = fabsf(dxr), ady = fabsf(dyr), adz = fabsf(dzr);
    int axis = (adx >= ady && adx >= adz) ? 0 : ((ady >= adz) ? 1 : 2);

    float oD = (axis == 0) ? ox : ((axis == 1) ? oy : oz);
    float oU = (axis == 0) ? oy : ox;
    float oV = (axis == 2) ? oy : oz;
    float iD = (axis == 0) ? ivx : ((axis == 1) ? ivy : ivz);
    float iU = (axis == 0) ? ivy : ivx;
    float iV = (axis == 2) ? ivy : ivz;
    float dUr = (axis == 0) ? dyr : dxr;
    float dVr = (axis == 2) ? dyr : dzr;

    const int sD = (iD >= 0.0f) ? 1 : -1;
    const int sU = (iU >= 0.0f) ? 1 : -1;
    const int sV = (iV >= 0.0f) ? 1 : -1;
    const int exU = (sU > 0) ? 1 : 0;
    const int exV = (sV > 0) ? 1 : 0;

    // Slab j -> grid layer k in traversal order.
    const int k = (sD > 0) ? j : (GN - 1 - j);

    // Exact D-axis crossings of slab k.
    float pk0 = fmaf((float)k,       CELL, BMIN);
    float pk1 = fmaf((float)(k + 1), CELL, BMIN);
    float tA = (pk0 - oD) * iD;
    float tB = (pk1 - oD) * iD;
    float lDk = fminf(tA, tB);
    float nDk = fmaxf(tA, tB);
    float lD0 = fmaxf(lDk, 0.0f);

    float w0 = fmaxf(lDk, tEnter);
    float w1 = fminf(nDk, tExit);
    bool alive = (w1 > w0);

    // Early zero-fill of idx row (stores retire under the compute shadow).
    float* out_idx = out + (size_t)5 * R + (size_t)r * MAX_HITS;
    if (lane < MAX_HITS / 4)
        ((float4*)out_idx)[lane] = make_float4(0.0f, 0.0f, 0.0f, 0.0f);

    // ---- U axis: entry cell u0 (exact-crossing corrected) + exit cell u1 ----
    float pu = fmaf(dUr, w0, oU);
    int u0 = (int)floorf((pu - BMIN) * 8.0f);
    float lu0 = (fmaf((float)(u0 + 1 - exU), CELL, BMIN) - oU) * iU;
    float nu0 = (fmaf((float)(u0 + exU),     CELL, BMIN) - oU) * iU;
    if      (nu0 < w0) u0 += sU;       // floor undershot
    else if (lu0 > w0) u0 -= sU;       // floor overshot
    lu0 = (fmaf((float)(u0 + 1 - exU), CELL, BMIN) - oU) * iU;
    nu0 = (fmaf((float)(u0 + exU),     CELL, BMIN) - oU) * iU;
    bool stepU = (nu0 < w1);
    int   u1  = u0 + (stepU ? sU : 0);
    float lu1 = stepU ? nu0 : lu0;
    float nu1 = stepU ? ((fmaf((float)(u1 + exU), CELL, BMIN) - oU) * iU) : nu0;

    // ---- V axis ----
    float pv = fmaf(dVr, w0, oV);
    int v0 = (int)floorf((pv - BMIN) * 8.0f);
    float lv0 = (fmaf((float)(v0 + 1 - exV), CELL, BMIN) - oV) * iV;
    float nv0 = (fmaf((float)(v0 + exV),     CELL, BMIN) - oV) * iV;
    if      (nv0 < w0) v0 += sV;
    else if (lv0 > w0) v0 -= sV;
    lv0 = (fmaf((float)(v0 + 1 - exV), CELL, BMIN) - oV) * iV;
    nv0 = (fmaf((float)(v0 + exV),     CELL, BMIN) - oV) * iV;
    bool stepV = (nv0 < w1);
    int   v1  = v0 + (stepV ? sV : 0);
    float lv1 = stepV ? nv0 : lv0;
    float nv1 = stepV ? ((fmaf((float)(v1 + exV), CELL, BMIN) - oV) * iV) : nv0;

    // ---- this lane's V row: half 0 -> v0, half 1 -> v1 ----
    int   vH  = h ? v1  : v0;
    float lvH = h ? lv1 : lv0;
    float nvH = h ? nv1 : nv0;
    bool gateH = h ? stepV : true;      // half 1 only exists if V stepped
    bool inbVH = ((unsigned)vH < GN);
    bool inbU0 = ((unsigned)u0 < GN), inbU1 = ((unsigned)u1 < GN);

    // ---- two candidates: (u0, vH) then (u1, vH), exact slab arithmetic ----
    float tnA = fmaxf(fmaxf(lu0, lvH), lD0), tfA = fminf(fminf(nu0, nvH), nDk);
    float tnB = fmaxf(fmaxf(lu1, lvH), lD0), tfB = fminf(fminf(nu1, nvH), nDk);
    bool hitA = alive && gateH && inbU0 && inbVH && (tfA > tnA);
    bool hitB = alive && gateH && stepU && inbU1 && inbVH && (tfB > tnB);

    // Clamped indices for safe unconditional loads.
    int uc0 = min(GN - 1, max(0, u0)), uc1 = min(GN - 1, max(0, u1));
    int vcH = min(GN - 1, max(0, vH));

    #define VOXI(UC, VC) \
        ((((axis == 0) ? k : (UC)) * GN + ((axis == 0) ? (UC) : ((axis == 1) ? k : (VC)))) * GN \
         + ((axis == 2) ? k : (VC)))
    int voxA = VOXI(uc0, vcH);
    int voxB = VOXI(uc1, vcH);
    #undef VOXI

    // Unconditional loads (all L1-resident), gated composite.
    float sgA = __expf(__ldg(&vdens[voxA]));
    float aA0 = __ldg(&vcol[3 * voxA + 0]);
    float aA1 = __ldg(&vcol[3 * voxA + 1]);
    float aA2 = __ldg(&vcol[3 * voxA + 2]);
    float sgB = __expf(__ldg(&vdens[voxB]));
    float aB0 = __ldg(&vcol[3 * voxB + 0]);
    float aB1 = __ldg(&vcol[3 * voxB + 1]);
    float aB2 = __ldg(&vcol[3 * voxB + 2]);

    float alA = 1.0f - __expf(-sgA * (tfA - tnA));
    float alB = 1.0f - __expf(-sgB * (tfB - tnB));

    float Tl = 1.0f, lr = 0.0f, lg = 0.0f, lb = 0.0f, ldep = 0.0f;
    {
        float w = hitA ? (Tl * alA) : 0.0f;
        lr   = fmaf(w, aA0, lr);
        lg   = fmaf(w, aA1, lg);
        lb   = fmaf(w, aA2, lb);
        ldep = fmaf(w, 0.5f * (tnA + tfA), ldep);
        Tl  *= hitA ? (1.0f - alA + 1e-10f) : 1.0f;
    }
    {
        float w = hitB ? (Tl * alB) : 0.0f;
        lr   = fmaf(w, aB0, lr);
        lg   = fmaf(w, aB1, lg);
        lb   = fmaf(w, aB2, lb);
        ldep = fmaf(w, 0.5f * (tnB + tfB), ldep);
        Tl  *= hitB ? (1.0f - alB + 1e-10f) : 1.0f;
    }
    int cnt = (hitA ? 1 : 0) + (hitB ? 1 : 0);

    // ---- width-32 scans: hit-count prefix sum + transmittance prefix product
    float prod = Tl;
    int   csum = cnt;
    #pragma unroll
    for (int d = 1; d < 32; d <<= 1) {
        float p = __shfl_up_sync(FULL, prod, d);
        int   c = __shfl_up_sync(FULL, csum, d);
        if (lane >= d) { prod *= p; csum += c; }
    }
    float T0 = __shfl_up_sync(FULL, prod, 1);
    if (lane == 0) T0 = 1.0f;
    int base  = csum - cnt;
    int total = __shfl_sync(FULL, csum, 31);

    // ---- reductions: rgb/depth scale linearly with incoming T0 ----
    float sr = T0 * lr, sg2 = T0 * lg, sb = T0 * lb, sd = T0 * ldep;
    #pragma unroll
    for (int d = 16; d > 0; d >>= 1) {
        sr  += __shfl_xor_sync(FULL, sr,  d);
        sg2 += __shfl_xor_sync(FULL, sg2, d);
        sb  += __shfl_xor_sync(FULL, sb,  d);
        sd  += __shfl_xor_sync(FULL, sd,  d);
    }

    // ---- outputs ----
    __syncwarp(FULL);   // zero-fill (other lanes) before hit overwrites

    int p = base;
    if (hitA) out_idx[p++] = (float)voxA;
    if (hitB) out_idx[p++] = (float)voxB;

    if (lane == 0) {
        out[3 * r + 0] = sr;
        out[3 * r + 1] = sg2;
        out[3 * r + 2] = sb;
        out[(size_t)3 * R + r] = sd;
        out[(size_t)4 * R + r] = (float)total;
    }
}

extern "C" void kernel_launch(void* const* d_in, const int* in_sizes, int n_in,
                              void* d_out, int out_size)
{
    const float* ro    = (const float*)d_in[0];
    const float* rd    = (const float*)d_in[1];
    const float* vdens = (const float*)d_in[4];
    const float* vcol  = (const float*)d_in[5];
    float* out = (float*)d_out;

    int R = in_sizes[0] / 3;
    long long total_threads = (long long)R * 32;
    int blocks = (int)((total_threads + BLOCK - 1) / BLOCK);
    svraster_kernel<<<blocks, BLOCK>>>(ro, rd, vdens, vcol, out, R);
}

// round 10
// speedup vs baseline: 1.0814x; 1.0543x over previous
#include <cuda_runtime.h>
#include <math.h>

// SVRaster: 4096 rays vs 16^3 regular voxel grid on [-1,1]^3.
//
// ONE WARP PER RAY. Lane l = 2*j + h: slab j (traversal order along the
// dominant axis D), half h. Since |dU|,|dV| <= |dD| a slab has at most one
// U crossing and one V crossing => visited cells lie in {u0,u1} x {v0,v1}.
// Half 0 tests (u0,v0),(u1,v0); half 1 tests (u0,v1),(u1,v1). The two middle
// candidates are mutually exclusive, so lane order == exact tn order.
// All hit decisions use the EXACT reference slab arithmetic (planes
// i*0.125-1 are exact fp32 == ctr +/- half): hit set & order == reference.
// Compositing uses linearity in incoming transmittance: local composite with
// T=1, then a width-32 shuffle prefix-product supplies each lane's true T0.
// Hit placement uses ballots (order = (lane, A, B)) instead of an int scan.
// The body is templated on the dominant axis (warp-uniform branch).

#define GN       16
#define CELL     0.125f
#define BMIN     (-1.0f)
#define MAX_HITS 100
#define BLOCK    128

__device__ __forceinline__ float safe_dir(float d) {
    return (fabsf(d) < 1e-8f) ? ((d >= 0.0f) ? 1e-8f : -1e-8f) : d;
}

template<int AX>
__device__ __forceinline__ int voxi(int k, int u, int v) {
    if (AX == 0) return (k * GN + u) * GN + v;   // D=x, U=y, V=z
    if (AX == 1) return (u * GN + k) * GN + v;   // D=y, U=x, V=z
    return (u * GN + v) * GN + k;                // D=z, U=x, V=y
}

template<int AX>
__device__ __forceinline__ void trace_body(
    int lane, int r, int R,
    float oD, float oU, float oV,
    float iD, float iU, float iV,
    float dUr, float dVr,
    float tEnter, float tExit,
    const float* __restrict__ vdens,
    const float* __restrict__ vcol,
    float* __restrict__ out,
    float* __restrict__ out_idx)
{
    const unsigned FULL = 0xffffffffu;
    const int j = lane >> 1;
    const int h = lane & 1;

    const int sD = (iD >= 0.0f) ? 1 : -1;
    const int sU = (iU >= 0.0f) ? 1 : -1;
    const int sV = (iV >= 0.0f) ? 1 : -1;
    const int exU = (sU > 0) ? 1 : 0;
    const int exV = (sV > 0) ? 1 : 0;

    // Slab j -> grid layer k in traversal order.
    const int k = (sD > 0) ? j : (GN - 1 - j);

    // Exact D-axis crossings of slab k.
    float pk0 = fmaf((float)k,       CELL, BMIN);
    float pk1 = fmaf((float)(k + 1), CELL, BMIN);
    float tA = (pk0 - oD) * iD;
    float tB = (pk1 - oD) * iD;
    float lDk = fminf(tA, tB);
    float nDk = fmaxf(tA, tB);
    float lD0 = fmaxf(lDk, 0.0f);

    float w0 = fmaxf(lDk, tEnter);
    float w1 = fminf(nDk, tExit);
    bool alive = (w1 > w0);

    // ---- U axis: entry cell u0 (exact-crossing corrected) + exit cell u1 ----
    float pu = fmaf(dUr, w0, oU);
    int u0 = (int)floorf((pu - BMIN) * 8.0f);
    float lu0 = (fmaf((float)(u0 + 1 - exU), CELL, BMIN) - oU) * iU;
    float nu0 = (fmaf((float)(u0 + exU),     CELL, BMIN) - oU) * iU;
    if      (nu0 < w0) u0 += sU;       // floor undershot
    else if (lu0 > w0) u0 -= sU;       // floor overshot
    lu0 = (fmaf((float)(u0 + 1 - exU), CELL, BMIN) - oU) * iU;
    nu0 = (fmaf((float)(u0 + exU),     CELL, BMIN) - oU) * iU;
    bool stepU = (nu0 < w1);
    int   u1  = u0 + (stepU ? sU : 0);
    float lu1 = stepU ? nu0 : lu0;
    float nu1 = stepU ? ((fmaf((float)(u1 + exU), CELL, BMIN) - oU) * iU) : nu0;

    // ---- V axis ----
    float pv = fmaf(dVr, w0, oV);
    int v0 = (int)floorf((pv - BMIN) * 8.0f);
    float lv0 = (fmaf((float)(v0 + 1 - exV), CELL, BMIN) - oV) * iV;
    float nv0 = (fmaf((float)(v0 + exV),     CELL, BMIN) - oV) * iV;
    if      (nv0 < w0) v0 += sV;
    else if (lv0 > w0) v0 -= sV;
    lv0 = (fmaf((float)(v0 + 1 - exV), CELL, BMIN) - oV) * iV;
    nv0 = (fmaf((float)(v0 + exV),     CELL, BMIN) - oV) * iV;
    bool stepV = (nv0 < w1);
    int   v1  = v0 + (stepV ? sV : 0);
    float lv1 = stepV ? nv0 : lv0;
    float nv1 = stepV ? ((fmaf((float)(v1 + exV), CELL, BMIN) - oV) * iV) : nv0;

    // ---- this lane's V row: half 0 -> v0, half 1 -> v1 ----
    int   vH  = h ? v1  : v0;
    float lvH = h ? lv1 : lv0;
    float nvH = h ? nv1 : nv0;
    bool gateH = h ? stepV : true;      // half 1 only exists if V stepped
    bool inbVH = ((unsigned)vH < GN);
    bool inbU0 = ((unsigned)u0 < GN), inbU1 = ((unsigned)u1 < GN);

    // ---- two candidates: (u0, vH) then (u1, vH), exact slab arithmetic ----
    float tnA = fmaxf(fmaxf(lu0, lvH), lD0), tfA = fminf(fminf(nu0, nvH), nDk);
    float tnB = fmaxf(fmaxf(lu1, lvH), lD0), tfB = fminf(fminf(nu1, nvH), nDk);
    bool hitA = alive && gateH && inbU0 && inbVH && (tfA > tnA);
    bool hitB = alive && gateH && stepU && inbU1 && inbVH && (tfB > tnB);

    // Clamped indices for safe unconditional loads.
    int uc0 = min(GN - 1, max(0, u0)), uc1 = min(GN - 1, max(0, u1));
    int vcH = min(GN - 1, max(0, vH));
    int voxA = voxi<AX>(k, uc0, vcH);
    int voxB = voxi<AX>(k, uc1, vcH);

    // Unconditional loads (all L1-resident), gated composite.
    float sgA = __expf(__ldg(&vdens[voxA]));
    float aA0 = __ldg(&vcol[3 * voxA + 0]);
    float aA1 = __ldg(&vcol[3 * voxA + 1]);
    float aA2 = __ldg(&vcol[3 * voxA + 2]);
    float sgB = __expf(__ldg(&vdens[voxB]));
    float aB0 = __ldg(&vcol[3 * voxB + 0]);
    float aB1 = __ldg(&vcol[3 * voxB + 1]);
    float aB2 = __ldg(&vcol[3 * voxB + 2]);

    float alA = 1.0f - __expf(-sgA * (tfA - tnA));
    float alB = 1.0f - __expf(-sgB * (tfB - tnB));

    float Tl = 1.0f, lr = 0.0f, lg = 0.0f, lb = 0.0f, ldep = 0.0f;
    {
        float w = hitA ? alA : 0.0f;              // Tl == 1 here
        lr   = fmaf(w, aA0, lr);
        lg   = fmaf(w, aA1, lg);
        lb   = fmaf(w, aA2, lb);
        ldep = fmaf(w, tnA + tfA, ldep);          // x2 depth; scaled at end
        Tl   = hitA ? (1.0f - alA + 1e-10f) : 1.0f;
    }
    {
        float w = hitB ? (Tl * alB) : 0.0f;
        lr   = fmaf(w, aB0, lr);
        lg   = fmaf(w, aB1, lg);
        lb   = fmaf(w, aB2, lb);
        ldep = fmaf(w, tnB + tfB, ldep);
        Tl  *= hitB ? (1.0f - alB + 1e-10f) : 1.0f;
    }

    // ---- ballots: hit order is (lane, A, B) -> base via popc below-mask ----
    unsigned mA = __ballot_sync(FULL, hitA);
    unsigned mB = __ballot_sync(FULL, hitB);
    unsigned below = (1u << lane) - 1u;
    int base  = __popc(mA & below) + __popc(mB & below);
    int total = __popc(mA) + __popc(mB);

    // ---- transmittance prefix product (width-32 shuffle scan) ----
    float prod = Tl;
    #pragma unroll
    for (int d = 1; d < 32; d <<= 1) {
        float p = __shfl_up_sync(FULL, prod, d);
        if (lane >= d) prod *= p;
    }
    float T0s = __shfl_up_sync(FULL, prod, 1);
    float T0 = lane ? T0s : 1.0f;

    // ---- reductions: rgb/depth scale linearly with incoming T0 ----
    float sr = T0 * lr, sg2 = T0 * lg, sb = T0 * lb, sd = T0 * ldep;
    #pragma unroll
    for (int d = 16; d > 0; d >>= 1) {
        sr  += __shfl_xor_sync(FULL, sr,  d);
        sg2 += __shfl_xor_sync(FULL, sg2, d);
        sb  += __shfl_xor_sync(FULL, sb,  d);
        sd  += __shfl_xor_sync(FULL, sd,  d);
    }

    // ---- outputs ----
    __syncwarp(FULL);   // zero-fill (other lanes) before hit overwrites

    int p = base;
    if (hitA) out_idx[p++] = (float)voxA;
    if (hitB) out_idx[p]   = (float)voxB;

    if (lane == 0) {
        out[3 * r + 0] = sr;
        out[3 * r + 1] = sg2;
        out[3 * r + 2] = sb;
        out[(size_t)3 * R + r] = 0.5f * sd;       // exact binary rescale
        out[(size_t)4 * R + r] = (float)total;
    }
}

__global__ void __launch_bounds__(BLOCK)
svraster_kernel(const float* __restrict__ ro,
                const float* __restrict__ rd,
                const float* __restrict__ vdens,
                const float* __restrict__ vcol,
                float* __restrict__ out,
                int R)
{
    const int tid  = threadIdx.x;
    const int lane = tid & 31;
    const int r    = (blockIdx.x * BLOCK + tid) >> 5;   // ray id (1 warp/ray)

    const float ox = ro[3 * r + 0], oy = ro[3 * r + 1], oz = ro[3 * r + 2];
    const float dxr = rd[3 * r + 0], dyr = rd[3 * r + 1], dzr = rd[3 * r + 2];

    const float ivx = 1.0f / safe_dir(dxr);
    const float ivy = 1.0f / safe_dir(dyr);
    const float ivz = 1.0f / safe_dir(dzr);

    // Scene-box slab (exact same planes as grid faces).
    float tx0 = (BMIN - ox) * ivx, tx1 = (1.0f - ox) * ivx;
    float ty0 = (BMIN - oy) * ivy, ty1 = (1.0f - oy) * ivy;
    float tz0 = (BMIN - oz) * ivz, tz1 = (1.0f - oz) * ivz;
    float tEnter = fmaxf(fmaxf(fminf(tx0, tx1), fminf(ty0, ty1)), fminf(tz0, tz1));
    float tExit  = fminf(fminf(fmaxf(tx0, tx1), fmaxf(ty0, ty1)), fmaxf(tz0, tz1));
    tEnter = fmaxf(tEnter, 0.0f);

    // Early zero-fill of idx row (stores retire under the compute shadow).
    float* out_idx = out + (size_t)5 * R + (size_t)r * MAX_HITS;
    if (lane < MAX_HITS / 4)
        ((float4*)out_idx)[lane] = make_float4(0.0f, 0.0f, 0.0f, 0.0f);

    // Dominant axis D = argmax |d| (warp-uniform -> uniform branch dispatch).
    float adx = fabsf(dxr), ady = fabsf(dyr), adz = fabsf(dzr);
    if (adx >= ady && adx >= adz) {
        trace_body<0>(lane, r, R, ox, oy, oz, ivx, ivy, ivz, dyr, dzr,
                      tEnter, tExit, vdens, vcol, out, out_idx);
    } else if (ady >= adz) {
        trace_body<1>(lane, r, R, oy, ox, oz, ivy, ivx, ivz, dxr, dzr,
                      tEnter, tExit, vdens, vcol, out, out_idx);
    } else {
        trace_body<2>(lane, r, R, oz, ox, oy, ivz, ivx, ivy, dxr, dyr,
                      tEnter, tExit, vdens, vcol, out, out_idx);
    }
}

extern "C" void kernel_launch(void* const* d_in, const int* in_sizes, int n_in,
                              void* d_out, int out_size)
{
    const float* ro    = (const float*)d_in[0];
    const float* rd    = (const float*)d_in[1];
    const float* vdens = (const float*)d_in[4];
    const float* vcol  = (const float*)d_in[5];
    float* out = (float*)d_out;

    int R = in_sizes[0] / 3;
    long long total_threads = (long long)R * 32;
    int blocks = (int)((total_threads + BLOCK - 1) / BLOCK);
    svraster_kernel<<<blocks, BLOCK>>>(ro, rd, vdens, vcol, out, R);
}